// round 1
// baseline (speedup 1.0000x reference)
#include <cuda_runtime.h>
#include <math.h>

#define NN 10000
#define EE 160000
#define CC 32
#define NB 128
#define HH 64
#define FD 512   // C * (1+3+5+7)

// ---------------- scratch (device globals; no allocation) ----------------
__device__ float g_h[(size_t)EE*HH];     // 41 MB  : hidden per edge
__device__ float g_sh[(size_t)EE*16];    // 10 MB  : spherical harmonics per edge
__device__ float g_w[(size_t)EE*FD];     // 328 MB : [w_all(384) | ew(128)] per edge
__device__ float g_fa[(size_t)NN*FD];    // 20 MB  : node features buf A
__device__ float g_fb[(size_t)NN*FD];    // 20 MB  : node features buf B
__device__ int   g_cnt[NN];
__device__ int   g_off[NN+1];
__device__ int   g_eid[EE];

// ---------------- CSR build ----------------
__global__ void k_zero_cnt() {
    int i = blockIdx.x*blockDim.x + threadIdx.x;
    if (i < NN) g_cnt[i] = 0;
}

__global__ void k_hist(const int* __restrict__ ei) {
    int e = blockIdx.x*blockDim.x + threadIdx.x;
    if (e < EE) atomicAdd(&g_cnt[ei[EE + e]], 1);
}

__global__ void k_scan() {
    __shared__ int sdat[1024];
    __shared__ int carry;
    int tid = threadIdx.x;
    if (tid == 0) { carry = 0; g_off[0] = 0; }
    __syncthreads();
    for (int base = 0; base < NN; base += 1024) {
        int i = base + tid;
        int v = (i < NN) ? g_cnt[i] : 0;
        sdat[tid] = v;
        __syncthreads();
        for (int o = 1; o < 1024; o <<= 1) {
            int t = (tid >= o) ? sdat[tid - o] : 0;
            __syncthreads();
            sdat[tid] += t;
            __syncthreads();
        }
        int incl = sdat[tid] + carry;
        if (i < NN) g_off[i+1] = incl;
        __syncthreads();
        if (tid == 1023) carry = incl;
        __syncthreads();
    }
}

__global__ void k_fill(const int* __restrict__ ei) {
    int e = blockIdx.x*blockDim.x + threadIdx.x;
    if (e < EE) {
        int d = ei[EE + e];
        int p = atomicAdd(&g_cnt[d], 1);
        g_eid[g_off[d] + p] = e;
    }
}

// ---------------- edge geometry + radial basis + first MLP layer ----------------
// block = 256 threads = 8 warps; each warp handles 16 edges; block covers 128 edges.
__global__ void k_geom(const float* __restrict__ pos, const float* __restrict__ rw1,
                       const float* __restrict__ rb1, const int* __restrict__ ei) {
    __shared__ float s_rw1[NB*HH];      // 32 KB
    __shared__ float s_rb[8][NB];       // 4 KB
    int tid = threadIdx.x;
    for (int i = tid; i < NB*HH; i += 256) s_rw1[i] = rw1[i];
    __syncthreads();

    int wid = tid >> 5, lane = tid & 31;
    int ebase = blockIdx.x*128 + wid*16;

    for (int j = 0; j < 16; j++) {
        int e = ebase + j;
        int sn = ei[e], dn = ei[EE + e];
        float vx = pos[dn*3+0] - pos[sn*3+0];
        float vy = pos[dn*3+1] - pos[sn*3+1];
        float vz = pos[dn*3+2] - pos[sn*3+2];
        float r2 = vx*vx + vy*vy + vz*vz + 1e-12f;
        float r  = sqrtf(r2);
        float inv_r = 1.0f / r;
        float x = vx*inv_r, y = vy*inv_r, z = vz*inv_r;

        if (lane < 16) {
            const float s3  = 1.7320508075688772f;
            const float s15 = 3.872983346207417f;
            const float s5h = 1.118033988749895f;
            const float s15h= 1.9364916731037085f;
            const float c1  = 2.091650066335189f;
            const float c2  = 10.246950765959598f;
            const float c3  = 1.6201851746019651f;
            const float c4  = 1.3228756555322954f;
            const float c5  = 5.123475382979799f;
            float sv;
            switch (lane) {
                case 0:  sv = 1.0f; break;
                case 1:  sv = s3*x; break;
                case 2:  sv = s3*y; break;
                case 3:  sv = s3*z; break;
                case 4:  sv = s15*x*y; break;
                case 5:  sv = s15*y*z; break;
                case 6:  sv = s5h*(3.0f*z*z - 1.0f); break;
                case 7:  sv = s15*x*z; break;
                case 8:  sv = s15h*(x*x - y*y); break;
                case 9:  sv = c1*y*(3.0f*x*x - y*y); break;
                case 10: sv = c2*x*y*z; break;
                case 11: sv = c3*y*(5.0f*z*z - 1.0f); break;
                case 12: sv = c4*(5.0f*z*z*z - 3.0f*z); break;
                case 13: sv = c3*x*(5.0f*z*z - 1.0f); break;
                case 14: sv = c5*z*(x*x - y*y); break;
                default: sv = c1*x*(x*x - 3.0f*y*y); break;
            }
            g_sh[(size_t)e*16 + lane] = sv;
        }

        float u = fminf(r * 0.2f, 1.0f);                 // r / RC, RC = 5
        float env = 0.5f * (cospif(u) + 1.0f);
        float scale = env * 0.6324555320336759f * inv_r; // sqrt(2/RC)

        #pragma unroll
        for (int q = 0; q < 4; q++) {
            int i = lane + q*32;
            s_rb[wid][i] = scale * sinpif((float)(i+1) * u);
        }
        __syncwarp();

        float a0 = 0.f, a1 = 0.f;
        #pragma unroll 8
        for (int i = 0; i < NB; i++) {
            float rbv = s_rb[wid][i];
            float2 w = *(const float2*)&s_rw1[i*HH + 2*lane];
            a0 += rbv * w.x;
            a1 += rbv * w.y;
        }
        a0 += rb1[2*lane];
        a1 += rb1[2*lane+1];
        a0 = a0 / (1.0f + expf(-a0));   // silu
        a1 = a1 / (1.0f + expf(-a1));
        ((float2*)&g_h[(size_t)e*HH])[lane] = make_float2(a0, a1);
        __syncwarp();
    }
}

// ---------------- GEMM: g_w = g_h (E x 64) @ [rw2 | edge_w] (64 x 512) + bias ----------------
// BM=64, BN=128, BK=64 (full K). 256 threads, thread tile 4x8.
__global__ void k_gemm(const float* __restrict__ rw2, const float* __restrict__ edge_w,
                       const float* __restrict__ rb2, const float* __restrict__ edge_b) {
    __shared__ float As[64*64];     // 16 KB
    __shared__ float Bs[64*128];    // 32 KB
    int tid = threadIdx.x;
    int bx = blockIdx.x, by = blockIdx.y;

    #pragma unroll
    for (int p = 0; p < 16; p++) {
        int li = tid + p*256;
        int row = li >> 6, k = li & 63;
        As[li] = g_h[(size_t)(bx*64 + row)*64 + k];
    }
    #pragma unroll
    for (int p = 0; p < 32; p++) {
        int li = tid + p*256;
        int k = li >> 7, cn = li & 127;
        int jg = by*128 + cn;
        Bs[li] = (jg < 384) ? rw2[k*384 + jg] : edge_w[k*128 + (jg - 384)];
    }
    __syncthreads();

    int ty = tid >> 4, tx = tid & 15;
    float acc[4][8];
    #pragma unroll
    for (int i = 0; i < 4; i++)
        #pragma unroll
        for (int jj = 0; jj < 8; jj++) acc[i][jj] = 0.f;

    #pragma unroll 4
    for (int k = 0; k < 64; k++) {
        float a[4];
        #pragma unroll
        for (int rr = 0; rr < 4; rr++) a[rr] = As[(ty*4 + rr)*64 + k];
        float4 b0 = *(const float4*)&Bs[k*128 + tx*8];
        float4 b1 = *(const float4*)&Bs[k*128 + tx*8 + 4];
        #pragma unroll
        for (int rr = 0; rr < 4; rr++) {
            acc[rr][0] += a[rr]*b0.x;  acc[rr][1] += a[rr]*b0.y;
            acc[rr][2] += a[rr]*b0.z;  acc[rr][3] += a[rr]*b0.w;
            acc[rr][4] += a[rr]*b1.x;  acc[rr][5] += a[rr]*b1.y;
            acc[rr][6] += a[rr]*b1.z;  acc[rr][7] += a[rr]*b1.w;
        }
    }

    float bias[8];
    #pragma unroll
    for (int cc = 0; cc < 8; cc++) {
        int jg = by*128 + tx*8 + cc;
        bias[cc] = (jg < 384) ? rb2[jg] : edge_b[jg - 384];
    }
    #pragma unroll
    for (int rr = 0; rr < 4; rr++) {
        size_t base = (size_t)(bx*64 + ty*4 + rr)*FD + by*128 + tx*8;
        float4 o0 = make_float4(acc[rr][0]+bias[0], acc[rr][1]+bias[1],
                                acc[rr][2]+bias[2], acc[rr][3]+bias[3]);
        float4 o1 = make_float4(acc[rr][4]+bias[4], acc[rr][5]+bias[5],
                                acc[rr][6]+bias[6], acc[rr][7]+bias[7]);
        *(float4*)&g_w[base]     = o0;
        *(float4*)&g_w[base + 4] = o1;
    }
}

// ---------------- node feature init ----------------
__global__ void k_init(const float* __restrict__ node_embed, const int* __restrict__ species) {
    int i = blockIdx.x*blockDim.x + threadIdx.x;
    if (i < NN*FD) {
        int n = i >> 9, idx = i & 511;
        g_fa[i] = (idx < 32) ? node_embed[species[n]*32 + idx] : 0.f;
    }
}

// ---------------- one message-passing layer ----------------
// block = 1 node, 128 threads; warp l in {0..3} owns angular channel l (dim = 2l+1).
// f layout per node: offset 32*l*l + c*(2l+1) + m.
__global__ void k_layer(int t,
                        const float* __restrict__ sw, const float* __restrict__ mw,
                        const float* __restrict__ gw, const int* __restrict__ ei,
                        float* __restrict__ outp) {
    const float* fp = (t == 1) ? g_fb : g_fa;
    float* fn = (t == 0) ? g_fb : ((t == 1) ? g_fa : outp);

    __shared__ float s_f[FD], s_agg[FD], s_new[FD], s_gate[32];
    int n = blockIdx.x;
    int tid = threadIdx.x, l = tid >> 5, lane = tid & 31;
    int dim = 2*l + 1;
    int off = 32*l*l;     // 0,32,128,288
    int shoff = l*l;      // 0,1,4,9

    #pragma unroll
    for (int k = 0; k < 4; k++)
        s_f[tid + k*128] = fp[(size_t)n*FD + tid + k*128];

    // gather + aggregate (accumulators in registers per warp)
    float acc[7] = {0,0,0,0,0,0,0};
    int e0 = g_off[n], e1 = g_off[n+1];
    for (int ii = e0; ii < e1; ii++) {
        int e = g_eid[ii];
        float w = g_w[(size_t)e*FD + t*128 + l*32 + lane];
        int srcn = ei[e];
        float s = fp[(size_t)srcn*FD + lane];   // f0 component = index c
        float ws = w * s;
        const float* shp = &g_sh[(size_t)e*16 + shoff];
        #pragma unroll
        for (int m = 0; m < 7; m++)
            if (m < dim) acc[m] += ws * shp[m];
    }
    #pragma unroll
    for (int m = 0; m < 7; m++)
        if (m < dim) s_agg[off + lane*dim + m] = acc[m];
    __syncthreads();

    // einsum: new[l][d,m] = sum_c f[l][c,m]*sw[c,d] + agg[l][c,m]*mw[c,d]   (lane = d)
    float o[7] = {0,0,0,0,0,0,0};
    const float* swp = sw + (size_t)((t*4 + l)*32)*32;
    const float* mwp = mw + (size_t)((t*4 + l)*32)*32;
    for (int c = 0; c < 32; c++) {
        float wsv = swp[c*32 + lane];
        float wmv = mwp[c*32 + lane];
        #pragma unroll
        for (int m = 0; m < 7; m++)
            if (m < dim) {
                o[m] += s_f[off + c*dim + m]*wsv + s_agg[off + c*dim + m]*wmv;
            }
    }
    #pragma unroll
    for (int m = 0; m < 7; m++)
        if (m < dim) s_new[off + lane*dim + m] = o[m];
    __syncthreads();

    // gate from new0
    if (l == 0) {
        float g = 0.f;
        #pragma unroll 4
        for (int c = 0; c < 32; c++)
            g += s_new[c] * gw[(t*32 + c)*32 + lane];
        s_gate[lane] = 1.0f / (1.0f + expf(-g));
    }
    __syncthreads();

    // activation / gating + writeout
    #pragma unroll
    for (int k = 0; k < 4; k++) {
        int idx = tid + k*128;
        float v = s_new[idx];
        float outv;
        if (idx < 32) {
            outv = v / (1.0f + expf(-v));          // silu on l=0
        } else {
            int d;
            if (idx < 128)      d = (idx - 32) / 3;
            else if (idx < 288) d = (idx - 128) / 5;
            else                d = (idx - 288) / 7;
            outv = v * s_gate[d];
        }
        fn[(size_t)n*FD + idx] = outv;
    }
}

// ---------------- edge output ----------------
__global__ void k_edge_out(const int* __restrict__ ei, const float* __restrict__ nodef,
                           float* __restrict__ out) {
    __shared__ float s_g[32], s_sh[16], s_ew[128];
    int e = blockIdx.x, tid = threadIdx.x;
    int sn = ei[e], dn = ei[EE + e];
    if (tid < 32)
        s_g[tid] = nodef[(size_t)sn*FD + tid] + nodef[(size_t)dn*FD + tid];
    else if (tid < 48)
        s_sh[tid - 32] = g_sh[(size_t)e*16 + (tid - 32)];
    s_ew[tid] = g_w[(size_t)e*FD + 384 + tid];
    __syncthreads();

    float* orow = out + (size_t)(NN + e)*FD;
    #pragma unroll
    for (int k = 0; k < 4; k++) {
        int idx = tid + k*128;
        int l, c, m;
        if (idx < 32)       { l = 0; c = idx;       m = 0; }
        else if (idx < 128) { int r = idx - 32;  l = 1; c = r/3; m = r - 3*c; }
        else if (idx < 288) { int r = idx - 128; l = 2; c = r/5; m = r - 5*c; }
        else                { int r = idx - 288; l = 3; c = r/7; m = r - 7*c; }
        orow[idx] = s_ew[l*32 + c] * s_g[c] * s_sh[l*l + m];
    }
}

// ---------------- launch ----------------
extern "C" void kernel_launch(void* const* d_in, const int* in_sizes, int n_in,
                              void* d_out, int out_size) {
    const float* pos        = (const float*)d_in[0];
    const float* node_embed = (const float*)d_in[1];
    const float* rw1        = (const float*)d_in[2];
    const float* rb1        = (const float*)d_in[3];
    const float* rw2        = (const float*)d_in[4];
    const float* rb2        = (const float*)d_in[5];
    const float* self_w     = (const float*)d_in[6];
    const float* msg_w      = (const float*)d_in[7];
    const float* gate_w     = (const float*)d_in[8];
    const float* edge_w     = (const float*)d_in[9];
    const float* edge_b     = (const float*)d_in[10];
    const int*   species    = (const int*)d_in[11];
    const int*   ei         = (const int*)d_in[12];
    float* out = (float*)d_out;

    // CSR by dst
    k_zero_cnt<<<(NN+255)/256, 256>>>();
    k_hist<<<(EE+255)/256, 256>>>(ei);
    k_scan<<<1, 1024>>>();
    k_zero_cnt<<<(NN+255)/256, 256>>>();
    k_fill<<<(EE+255)/256, 256>>>(ei);

    // per-edge geometry, radial basis, hidden layer
    k_geom<<<EE/128, 256>>>(pos, rw1, rb1, ei);

    // second MLP layer -> [w_all | ew]
    dim3 gg(EE/64, 4);
    k_gemm<<<gg, 256>>>(rw2, edge_w, rb2, edge_b);

    // node features
    k_init<<<(NN*FD + 255)/256, 256>>>(node_embed, species);

    // 3 message-passing layers; last writes node rows of d_out directly
    for (int t = 0; t < 3; t++)
        k_layer<<<NN, 128>>>(t, self_w, msg_w, gate_w, ei, out);

    // edge rows of d_out
    k_edge_out<<<EE, 128>>>(ei, out, out);
}